// round 12
// baseline (speedup 1.0000x reference)
#include <cuda_runtime.h>
#include <cuda_bf16.h>

// ---------------------------------------------------------------------------
// DisableGateLSTM: B=64, T=512, E=256, H=512, C=4
// Phase 1: pre[t][row][b] = bias[row] + x_t @ W[:,512:768]^T   (268 MB scratch)
// Phase 2: persistent recurrence, 128 CTAs = 32 row-groups x 4 batch-columns.
//          Weights in REGISTERS, h tile via 2-group cp.async.cg pipeline,
//          pre via early LDG (off the critical path), per-column flag barrier.
// Phase 3: logits = (max_t h) @ fc_w^T + fc_b
// ---------------------------------------------------------------------------

#define T_SEQ 512
#define NB    64
#define NE    256
#define NH    512
#define NG    2048
#define RECUR_CTAS 128

typedef unsigned long long u64;

static __device__ float g_pre[(size_t)T_SEQ * NG * NB];   // [t][row][b]
static __device__ float g_h[2][NH * NB];                  // ping-pong h, [j][b]
static __device__ float g_hmax[NH * NB];                  // [j][b]
static __device__ int   g_flags[RECUR_CTAS];              // [bg][rg] progress flags
static __device__ int   g_count;                          // epilogue barrier
static __device__ int   g_sense;

// ---------------- f32x2 helpers ----------------
static __device__ __forceinline__ u64 fma2(u64 a, u64 b, u64 c) {
    u64 d;
    asm("fma.rn.f32x2 %0, %1, %2, %3;" : "=l"(d) : "l"(a), "l"(b), "l"(c));
    return d;
}
static __device__ __forceinline__ u64 add2(u64 a, u64 b) {
    u64 d;
    asm("add.rn.f32x2 %0, %1, %2;" : "=l"(d) : "l"(a), "l"(b));
    return d;
}
static __device__ __forceinline__ u64 pkdup(float a) {
    u64 r; asm("mov.b64 %0, {%1, %1};" : "=l"(r) : "f"(a)); return r;
}
static __device__ __forceinline__ float2 upk2(u64 a) {
    float2 f;
    asm("mov.b64 {%0, %1}, %2;" : "=f"(f.x), "=f"(f.y) : "l"(a));
    return f;
}
static __device__ __forceinline__ float sigf(float x) {
    return 1.f / (1.f + __expf(-x));
}
static __device__ __forceinline__ float tanh_fast(float x) {
    return 2.f / (1.f + __expf(-2.f * x)) - 1.f;
}
// cp.async.cg: L2-only path => coherent with other SMs' global stores
static __device__ __forceinline__ void cpa16(void* dst, const void* src) {
    unsigned s = (unsigned)__cvta_generic_to_shared(dst);
    asm volatile("cp.async.cg.shared.global [%0], [%1], 16;" :: "r"(s), "l"(src) : "memory");
}

// =====================================================================
// Phase 1: pre-GEMM.  grid = (16 j-tiles, 256 m-tiles), 256 threads.
// =====================================================================
__global__ void __launch_bounds__(256, 2) pre_gemm(
    const int* __restrict__ ids, const float* __restrict__ emb,
    const float* __restrict__ Wf, const float* __restrict__ bf,
    const float* __restrict__ Wi, const float* __restrict__ bi,
    const float* __restrict__ Wo, const float* __restrict__ bo,
    const float* __restrict__ Wc, const float* __restrict__ bc)
{
    __shared__ float As[2][16][256];   // [kk][2*j] duplicated pairs
    __shared__ float Bs[2][16][128];   // [kk][m]

    const int t  = threadIdx.x;
    const int gx = blockIdx.x;
    const int m0 = blockIdx.y * 128;
    const int tx = t & 15, ty = t >> 4;

    const float* W    = (gx < 4) ? Wf : (gx < 8) ? Wi : (gx < 12) ? Wo : Wc;
    const float* bias = (gx < 4) ? bf : (gx < 8) ? bi : (gx < 12) ? bo : bc;
    const int jg0 = (gx & 3) * 128;

    const int jA0 = t >> 2;
    const int jA1 = jA0 + 64;
    const int qA  = t & 3;
    const int ml0 = t >> 2;
    const int ml1 = ml0 + 64;
    const int mg0 = m0 + ml0, mg1 = m0 + ml1;
    const int id0 = ids[(mg0 & 63) * T_SEQ + (mg0 >> 6)];
    const int id1 = ids[(mg1 & 63) * T_SEQ + (mg1 >> 6)];

    u64 acc[8][4];
#pragma unroll
    for (int jj = 0; jj < 8; ++jj)
#pragma unroll
        for (int s = 0; s < 4; ++s) acc[jj][s] = 0ull;

    float4 a0, a1, b0v, b1v;
    {
        const int k0 = 0;
        a0  = *(const float4*)&W[(size_t)(jg0 + jA0) * 768 + 512 + k0 + qA * 4];
        a1  = *(const float4*)&W[(size_t)(jg0 + jA1) * 768 + 512 + k0 + qA * 4];
        b0v = *(const float4*)&emb[(size_t)id0 * NE + k0 + qA * 4];
        b1v = *(const float4*)&emb[(size_t)id1 * NE + k0 + qA * 4];
    }
    {
        const int st = 0;
        *(float2*)&As[st][qA*4+0][2*jA0] = make_float2(a0.x, a0.x);
        *(float2*)&As[st][qA*4+1][2*jA0] = make_float2(a0.y, a0.y);
        *(float2*)&As[st][qA*4+2][2*jA0] = make_float2(a0.z, a0.z);
        *(float2*)&As[st][qA*4+3][2*jA0] = make_float2(a0.w, a0.w);
        *(float2*)&As[st][qA*4+0][2*jA1] = make_float2(a1.x, a1.x);
        *(float2*)&As[st][qA*4+1][2*jA1] = make_float2(a1.y, a1.y);
        *(float2*)&As[st][qA*4+2][2*jA1] = make_float2(a1.z, a1.z);
        *(float2*)&As[st][qA*4+3][2*jA1] = make_float2(a1.w, a1.w);
        Bs[st][qA*4+0][ml0] = b0v.x; Bs[st][qA*4+1][ml0] = b0v.y;
        Bs[st][qA*4+2][ml0] = b0v.z; Bs[st][qA*4+3][ml0] = b0v.w;
        Bs[st][qA*4+0][ml1] = b1v.x; Bs[st][qA*4+1][ml1] = b1v.y;
        Bs[st][qA*4+2][ml1] = b1v.z; Bs[st][qA*4+3][ml1] = b1v.w;
    }
    __syncthreads();

    int st = 0;
    for (int c = 0; c < 16; ++c) {
        if (c < 15) {
            const int k0 = (c + 1) * 16;
            a0  = *(const float4*)&W[(size_t)(jg0 + jA0) * 768 + 512 + k0 + qA * 4];
            a1  = *(const float4*)&W[(size_t)(jg0 + jA1) * 768 + 512 + k0 + qA * 4];
            b0v = *(const float4*)&emb[(size_t)id0 * NE + k0 + qA * 4];
            b1v = *(const float4*)&emb[(size_t)id1 * NE + k0 + qA * 4];
        }
#pragma unroll 4
        for (int kk = 0; kk < 16; ++kk) {
            ulonglong2 A01 = *(const ulonglong2*)&As[st][kk][ty * 16 + 0];
            ulonglong2 A23 = *(const ulonglong2*)&As[st][kk][ty * 16 + 4];
            ulonglong2 A45 = *(const ulonglong2*)&As[st][kk][ty * 16 + 8];
            ulonglong2 A67 = *(const ulonglong2*)&As[st][kk][ty * 16 + 12];
            u64 af[8] = {A01.x, A01.y, A23.x, A23.y, A45.x, A45.y, A67.x, A67.y};
            u64 bfr[4];
#pragma unroll
            for (int s = 0; s < 4; ++s)
                bfr[s] = *(const u64*)&Bs[st][kk][tx * 2 + s * 32];
#pragma unroll
            for (int jj = 0; jj < 8; ++jj)
#pragma unroll
                for (int s = 0; s < 4; ++s)
                    acc[jj][s] = fma2(bfr[s], af[jj], acc[jj][s]);
        }
        if (c < 15) {
            const int sn = st ^ 1;
            *(float2*)&As[sn][qA*4+0][2*jA0] = make_float2(a0.x, a0.x);
            *(float2*)&As[sn][qA*4+1][2*jA0] = make_float2(a0.y, a0.y);
            *(float2*)&As[sn][qA*4+2][2*jA0] = make_float2(a0.z, a0.z);
            *(float2*)&As[sn][qA*4+3][2*jA0] = make_float2(a0.w, a0.w);
            *(float2*)&As[sn][qA*4+0][2*jA1] = make_float2(a1.x, a1.x);
            *(float2*)&As[sn][qA*4+1][2*jA1] = make_float2(a1.y, a1.y);
            *(float2*)&As[sn][qA*4+2][2*jA1] = make_float2(a1.z, a1.z);
            *(float2*)&As[sn][qA*4+3][2*jA1] = make_float2(a1.w, a1.w);
            Bs[sn][qA*4+0][ml0] = b0v.x; Bs[sn][qA*4+1][ml0] = b0v.y;
            Bs[sn][qA*4+2][ml0] = b0v.z; Bs[sn][qA*4+3][ml0] = b0v.w;
            Bs[sn][qA*4+0][ml1] = b1v.x; Bs[sn][qA*4+1][ml1] = b1v.y;
            Bs[sn][qA*4+2][ml1] = b1v.z; Bs[sn][qA*4+3][ml1] = b1v.w;
        }
        __syncthreads();
        st ^= 1;
    }

#pragma unroll
    for (int jj = 0; jj < 8; ++jj) {
        const int row = gx * 128 + ty * 8 + jj;
        const float bv = bias[(gx & 3) * 128 + ty * 8 + jj];
#pragma unroll
        for (int s = 0; s < 4; ++s) {
            float2 v = upk2(acc[jj][s]);
            v.x += bv; v.y += bv;
            const int m = m0 + tx * 2 + s * 32;
            const size_t off = ((size_t)(m >> 6) * NG + row) * NB + (m & 63);
            *(float2*)&g_pre[off] = v;
        }
    }
}

// =====================================================================
// Phase 2: persistent recurrence.  128 CTAs x 256 threads.
// CTA(bid): rg = bid>>2 owns h-rows [16rg,16rg+16); bg = bid&3 owns
// batches [16bg,16bg+16).  Thread t: rw = t>>3 (2 gate rows), ks = t&7.
// Weights in registers.  h tile: 2 cp.async groups (kk-halves) so the
// first half of compute overlaps the second half's load.  pre via LDG
// issued before the poll (consumed only at combine).
// smem: hs[64kk][8ks][20f] 40960B | red[8ks][64r][9 u64] 37120B
// =====================================================================
__global__ void __launch_bounds__(256) lstm_recur(
    const float* __restrict__ Wf, const float* __restrict__ Wi,
    const float* __restrict__ Wo, const float* __restrict__ Wc)
{
    extern __shared__ float smem[];
    float* hs  = smem;                      // 64*8*20 = 10240 f (40960 B)
    u64*   red = (u64*)(smem + 10240);      // 8*580   = 4640 u64 (37120 B)

    const int t   = threadIdx.x;
    const int bid = blockIdx.x;
    const int rg  = bid >> 2;
    const int bg  = bid & 3;
    const int rw  = t >> 3;                 // 0..31: gate-row pair
    const int ks  = t & 7;                  // k-slice of 64
    const int jj  = t >> 3, bp = t & 7;     // combine mapping (t<128)

    // ---- load weights into registers (once) ----
    float wreg[2][64];
    {
        const int r0 = rw * 2;
        const int g  = r0 >> 4;
        const int jl = r0 & 15;
        const float* Wg = (g == 0) ? Wf : (g == 1) ? Wi : (g == 2) ? Wo : Wc;
#pragma unroll
        for (int rr = 0; rr < 2; ++rr) {
            const float* p = &Wg[(size_t)(rg * 16 + jl + rr) * 768 + ks * 64];
#pragma unroll
            for (int q = 0; q < 16; ++q) {
                float4 v = *(const float4*)(p + q * 4);
                wreg[rr][q * 4 + 0] = v.x; wreg[rr][q * 4 + 1] = v.y;
                wreg[rr][q * 4 + 2] = v.z; wreg[rr][q * 4 + 3] = v.w;
            }
        }
    }

    // ---- zero own slice of h[0], publish flag = 1 ----
    if (t < 128)
        *(float2*)&g_h[0][(rg * 16 + jj) * 64 + bg * 16 + 2 * bp] = make_float2(0.f, 0.f);
    __threadfence();
    __syncthreads();
    if (t == 0) ((volatile int*)g_flags)[bg * 32 + rg] = 1;

    float cva = 0.f, cvb = 0.f;
    float hma = -1e30f, hmb = -1e30f;

    for (int step = 0; step < T_SEQ; ++step) {
        // ---- pre slice via LDG, issued early, consumed at combine ----
        float2 pv[4];
        if (t < 128) {
            const float* pbase =
                g_pre + ((size_t)step * NG + rg * 16 + jj) * 64 + bg * 16 + 2 * bp;
#pragma unroll
            for (int g = 0; g < 4; ++g)
                pv[g] = *(const float2*)(pbase + (size_t)g * (512 * 64));
        }

        // ---- wait: own column's 32 CTAs have published step's h ----
        if (t < 32) {
            volatile int* fl = g_flags + bg * 32;
            while (fl[t] < step + 1) { }
        }
        __syncthreads();

        // ---- load h column tile as 2 groups (kk 0..31, kk 32..63) ----
        {
            const float* hin = g_h[step & 1];
#pragma unroll
            for (int i = 0; i < 4; ++i) {
                const int c   = i * 256 + t;
                const int kk  = c >> 5;          // 0..31
                const int r   = c & 31;
                const int kss = r >> 2, q = r & 3;
                cpa16(hs + (kk * 8 + kss) * 20 + q * 4,
                      hin + (kss * 64 + kk) * 64 + bg * 16 + q * 4);
            }
            asm volatile("cp.async.commit_group;" ::: "memory");
#pragma unroll
            for (int i = 0; i < 4; ++i) {
                const int c   = i * 256 + t;
                const int kk  = 32 + (c >> 5);   // 32..63
                const int r   = c & 31;
                const int kss = r >> 2, q = r & 3;
                cpa16(hs + (kk * 8 + kss) * 20 + q * 4,
                      hin + (kss * 64 + kk) * 64 + bg * 16 + q * 4);
            }
            asm volatile("cp.async.commit_group;" ::: "memory");
        }

        // ---- compute: 2 rows x 8 b-pairs, first half overlaps 2nd load ----
        u64 acc[2][8];
#pragma unroll
        for (int rr = 0; rr < 2; ++rr)
#pragma unroll
            for (int p = 0; p < 8; ++p) acc[rr][p] = 0ull;

#pragma unroll
        for (int half = 0; half < 2; ++half) {
            if (half == 0) asm volatile("cp.async.wait_group 1;" ::: "memory");
            else           asm volatile("cp.async.wait_group 0;" ::: "memory");
            __syncthreads();
#pragma unroll
            for (int kk = half * 32; kk < half * 32 + 32; ++kk) {
                const float* hrow = hs + (kk * 8 + ks) * 20;
                ulonglong2 ha = *(const ulonglong2*)(hrow + 0);
                ulonglong2 hb = *(const ulonglong2*)(hrow + 4);
                ulonglong2 hc = *(const ulonglong2*)(hrow + 8);
                ulonglong2 hd = *(const ulonglong2*)(hrow + 12);
                const u64 w0 = pkdup(wreg[0][kk]);
                const u64 w1 = pkdup(wreg[1][kk]);
                acc[0][0] = fma2(ha.x, w0, acc[0][0]);
                acc[0][1] = fma2(ha.y, w0, acc[0][1]);
                acc[0][2] = fma2(hb.x, w0, acc[0][2]);
                acc[0][3] = fma2(hb.y, w0, acc[0][3]);
                acc[0][4] = fma2(hc.x, w0, acc[0][4]);
                acc[0][5] = fma2(hc.y, w0, acc[0][5]);
                acc[0][6] = fma2(hd.x, w0, acc[0][6]);
                acc[0][7] = fma2(hd.y, w0, acc[0][7]);
                acc[1][0] = fma2(ha.x, w1, acc[1][0]);
                acc[1][1] = fma2(ha.y, w1, acc[1][1]);
                acc[1][2] = fma2(hb.x, w1, acc[1][2]);
                acc[1][3] = fma2(hb.y, w1, acc[1][3]);
                acc[1][4] = fma2(hc.x, w1, acc[1][4]);
                acc[1][5] = fma2(hc.y, w1, acc[1][5]);
                acc[1][6] = fma2(hd.x, w1, acc[1][6]);
                acc[1][7] = fma2(hd.y, w1, acc[1][7]);
            }
        }

        // ---- store k-partials: red[ks*580 + r*9 + p] ----
#pragma unroll
        for (int rr = 0; rr < 2; ++rr)
#pragma unroll
            for (int p = 0; p < 8; ++p)
                red[ks * 580 + (rw * 2 + rr) * 9 + p] = acc[rr][p];
        __syncthreads();

        // ---- combine + pointwise cell (threads 0..127) ----
        if (t < 128) {
            float2 gs[4];
#pragma unroll
            for (int g = 0; g < 4; ++g) {
                const int rbase = (g * 16 + jj) * 9 + bp;
                u64 s0 = add2(red[0 * 580 + rbase], red[1 * 580 + rbase]);
                u64 s1 = add2(red[2 * 580 + rbase], red[3 * 580 + rbase]);
                u64 s2 = add2(red[4 * 580 + rbase], red[5 * 580 + rbase]);
                u64 s3 = add2(red[6 * 580 + rbase], red[7 * 580 + rbase]);
                u64 sum = add2(add2(s0, s1), add2(s2, s3));
                float2 v = upk2(sum);
                gs[g] = make_float2(v.x + pv[g].x, v.y + pv[g].y);
            }
            const float fa = sigf(gs[0].x), fb = sigf(gs[0].y);
            const float ia = sigf(gs[1].x), ib = sigf(gs[1].y);
            const float oa = sigf(gs[2].x), ob = sigf(gs[2].y);
            const float ga = tanh_fast(gs[3].x), gb = tanh_fast(gs[3].y);
            cva = fa * cva + ia * ga;
            cvb = fb * cvb + ib * gb;
            const float ha = oa * tanh_fast(cva);
            const float hb = ob * tanh_fast(cvb);
            hma = fmaxf(hma, ha);
            hmb = fmaxf(hmb, hb);
            *(float2*)&g_h[(step + 1) & 1][(rg * 16 + jj) * 64 + bg * 16 + 2 * bp] =
                make_float2(ha, hb);
            __threadfence();
        }
        __syncthreads();
        if (t == 0) ((volatile int*)g_flags)[bg * 32 + rg] = step + 2;
    }

    // ---- epilogue: write hmax ----
    if (t < 128)
        *(float2*)&g_hmax[(rg * 16 + jj) * 64 + bg * 16 + 2 * bp] = make_float2(hma, hmb);

    // two centralized sense barriers (even count -> g_sense restored),
    // flag reset in between: no CTA can still be polling when reset lands.
    int sense = 0;
#pragma unroll
    for (int rep = 0; rep < 2; ++rep) {
        __threadfence();
        __syncthreads();
        if (t == 0) {
            sense ^= 1;
            if (atomicAdd(&g_count, 1) == RECUR_CTAS - 1) {
                *(volatile int*)&g_count = 0;
                __threadfence();
                *(volatile int*)&g_sense = sense;
            } else {
                while (*(volatile int*)&g_sense != sense) { }
            }
            __threadfence();
        }
        __syncthreads();
        if (rep == 0 && t == 0) g_flags[bg * 32 + rg] = 0;
    }
}

// =====================================================================
// Phase 3: logits[b][c] = fc_b[c] + sum_j hmax[j][b] * fc_w[c][j]
// =====================================================================
__global__ void fc_kernel(const float* __restrict__ fcw,
                          const float* __restrict__ fcb,
                          float* __restrict__ out)
{
    const int t = threadIdx.x;
    const int b = t & 63, c = t >> 6;
    float acc = 0.f;
#pragma unroll 8
    for (int j = 0; j < NH; ++j)
        acc += g_hmax[j * 64 + b] * fcw[c * NH + j];
    out[b * 4 + c] = acc + fcb[c];
}

// =====================================================================
extern "C" void kernel_launch(void* const* d_in, const int* in_sizes, int n_in,
                              void* d_out, int out_size)
{
    (void)in_sizes; (void)n_in; (void)out_size;
    const int*   ids = (const int*)  d_in[0];
    const float* emb = (const float*)d_in[1];
    const float* Wf  = (const float*)d_in[2];
    const float* bf  = (const float*)d_in[3];
    const float* Wi  = (const float*)d_in[4];
    const float* bi  = (const float*)d_in[5];
    const float* Wo  = (const float*)d_in[6];
    const float* bo  = (const float*)d_in[7];
    const float* Wc  = (const float*)d_in[8];
    const float* bc  = (const float*)d_in[9];
    const float* fcw = (const float*)d_in[10];
    const float* fcb = (const float*)d_in[11];
    float* out = (float*)d_out;

    // hs 40960 + red 37120 = 78080 B
    const int recur_smem = 78080;
    cudaFuncSetAttribute(lstm_recur, cudaFuncAttributeMaxDynamicSharedMemorySize, recur_smem);

    pre_gemm<<<dim3(16, 256), 256>>>(ids, emb, Wf, bf, Wi, bi, Wo, bo, Wc, bc);
    lstm_recur<<<RECUR_CTAS, 256, recur_smem>>>(Wf, Wi, Wo, Wc);
    fc_kernel<<<1, 256>>>(fcw, fcb, out);
}

// round 13
// speedup vs baseline: 1.4933x; 1.4933x over previous
#include <cuda_runtime.h>
#include <cuda_bf16.h>

// ---------------------------------------------------------------------------
// DisableGateLSTM: B=64, T=512, E=256, H=512, C=4
// Phase 1: pre[t][row][b] = bias[row] + x_t @ W[:,512:768]^T   (268 MB scratch)
// Phase 2: persistent recurrence, 128 CTAs = 32 row-groups x 4 batch-columns.
//          Weights in REGISTERS, h tile via cp.async.cg, pre double-buffered
//          in smem (prefetched one step ahead), per-column flag barrier,
//          single-fence publish.
// Phase 3: logits = (max_t h) @ fc_w^T + fc_b
// ---------------------------------------------------------------------------

#define T_SEQ 512
#define NB    64
#define NE    256
#define NH    512
#define NG    2048
#define RECUR_CTAS 128

typedef unsigned long long u64;

static __device__ float g_pre[(size_t)T_SEQ * NG * NB];   // [t][row][b]
static __device__ float g_h[2][NH * NB];                  // ping-pong h, [j][b]
static __device__ float g_hmax[NH * NB];                  // [j][b]
static __device__ int   g_flags[RECUR_CTAS];              // [bg][rg] progress flags
static __device__ int   g_count;                          // epilogue barrier
static __device__ int   g_sense;

// ---------------- f32x2 helpers ----------------
static __device__ __forceinline__ u64 fma2(u64 a, u64 b, u64 c) {
    u64 d;
    asm("fma.rn.f32x2 %0, %1, %2, %3;" : "=l"(d) : "l"(a), "l"(b), "l"(c));
    return d;
}
static __device__ __forceinline__ u64 add2(u64 a, u64 b) {
    u64 d;
    asm("add.rn.f32x2 %0, %1, %2;" : "=l"(d) : "l"(a), "l"(b));
    return d;
}
static __device__ __forceinline__ u64 pkdup(float a) {
    u64 r; asm("mov.b64 %0, {%1, %1};" : "=l"(r) : "f"(a)); return r;
}
static __device__ __forceinline__ float2 upk2(u64 a) {
    float2 f;
    asm("mov.b64 {%0, %1}, %2;" : "=f"(f.x), "=f"(f.y) : "l"(a));
    return f;
}
static __device__ __forceinline__ float sigf(float x) {
    return 1.f / (1.f + __expf(-x));
}
static __device__ __forceinline__ float tanh_fast(float x) {
    return 2.f / (1.f + __expf(-2.f * x)) - 1.f;
}
// cp.async.cg: L2-only path => coherent with other SMs' global stores
static __device__ __forceinline__ void cpa16(void* dst, const void* src) {
    unsigned s = (unsigned)__cvta_generic_to_shared(dst);
    asm volatile("cp.async.cg.shared.global [%0], [%1], 16;" :: "r"(s), "l"(src) : "memory");
}

// =====================================================================
// Phase 1: pre-GEMM (R11 version: ~832us, fma 52%)
// =====================================================================
__global__ void __launch_bounds__(256, 2) pre_gemm(
    const int* __restrict__ ids, const float* __restrict__ emb,
    const float* __restrict__ Wf, const float* __restrict__ bf,
    const float* __restrict__ Wi, const float* __restrict__ bi,
    const float* __restrict__ Wo, const float* __restrict__ bo,
    const float* __restrict__ Wc, const float* __restrict__ bc)
{
    __shared__ float As[2][16][256];   // [kk][2*j] duplicated pairs
    __shared__ float Bs[2][16][128];   // [kk][m]

    const int t  = threadIdx.x;
    const int gx = blockIdx.x;
    const int m0 = blockIdx.y * 128;
    const int tx = t & 15, ty = t >> 4;

    const float* W    = (gx < 4) ? Wf : (gx < 8) ? Wi : (gx < 12) ? Wo : Wc;
    const float* bias = (gx < 4) ? bf : (gx < 8) ? bi : (gx < 12) ? bo : bc;
    const int jg0 = (gx & 3) * 128;

    const int jA0 = t >> 2;
    const int jA1 = jA0 + 64;
    const int qA  = t & 3;
    const int ml0 = t >> 2;
    const int ml1 = ml0 + 64;
    const int mg0 = m0 + ml0, mg1 = m0 + ml1;
    const int id0 = ids[(mg0 & 63) * T_SEQ + (mg0 >> 6)];
    const int id1 = ids[(mg1 & 63) * T_SEQ + (mg1 >> 6)];

    u64 acc[8][4];
#pragma unroll
    for (int jj = 0; jj < 8; ++jj)
#pragma unroll
        for (int s = 0; s < 4; ++s) acc[jj][s] = 0ull;

    float4 a0, a1, b0v, b1v;
    {
        const int k0 = 0;
        a0  = *(const float4*)&W[(size_t)(jg0 + jA0) * 768 + 512 + k0 + qA * 4];
        a1  = *(const float4*)&W[(size_t)(jg0 + jA1) * 768 + 512 + k0 + qA * 4];
        b0v = *(const float4*)&emb[(size_t)id0 * NE + k0 + qA * 4];
        b1v = *(const float4*)&emb[(size_t)id1 * NE + k0 + qA * 4];
    }
    {
        const int st = 0;
        As[st][qA*4+0][2*jA0] = a0.x; As[st][qA*4+0][2*jA0+1] = a0.x;
        As[st][qA*4+1][2*jA0] = a0.y; As[st][qA*4+1][2*jA0+1] = a0.y;
        As[st][qA*4+2][2*jA0] = a0.z; As[st][qA*4+2][2*jA0+1] = a0.z;
        As[st][qA*4+3][2*jA0] = a0.w; As[st][qA*4+3][2*jA0+1] = a0.w;
        As[st][qA*4+0][2*jA1] = a1.x; As[st][qA*4+0][2*jA1+1] = a1.x;
        As[st][qA*4+1][2*jA1] = a1.y; As[st][qA*4+1][2*jA1+1] = a1.y;
        As[st][qA*4+2][2*jA1] = a1.z; As[st][qA*4+2][2*jA1+1] = a1.z;
        As[st][qA*4+3][2*jA1] = a1.w; As[st][qA*4+3][2*jA1+1] = a1.w;
        Bs[st][qA*4+0][ml0] = b0v.x; Bs[st][qA*4+1][ml0] = b0v.y;
        Bs[st][qA*4+2][ml0] = b0v.z; Bs[st][qA*4+3][ml0] = b0v.w;
        Bs[st][qA*4+0][ml1] = b1v.x; Bs[st][qA*4+1][ml1] = b1v.y;
        Bs[st][qA*4+2][ml1] = b1v.z; Bs[st][qA*4+3][ml1] = b1v.w;
    }
    __syncthreads();

    int st = 0;
    for (int c = 0; c < 16; ++c) {
        if (c < 15) {
            const int k0 = (c + 1) * 16;
            a0  = *(const float4*)&W[(size_t)(jg0 + jA0) * 768 + 512 + k0 + qA * 4];
            a1  = *(const float4*)&W[(size_t)(jg0 + jA1) * 768 + 512 + k0 + qA * 4];
            b0v = *(const float4*)&emb[(size_t)id0 * NE + k0 + qA * 4];
            b1v = *(const float4*)&emb[(size_t)id1 * NE + k0 + qA * 4];
        }
#pragma unroll 4
        for (int kk = 0; kk < 16; ++kk) {
            ulonglong2 A01 = *(const ulonglong2*)&As[st][kk][ty * 16 + 0];
            ulonglong2 A23 = *(const ulonglong2*)&As[st][kk][ty * 16 + 4];
            ulonglong2 A45 = *(const ulonglong2*)&As[st][kk][ty * 16 + 8];
            ulonglong2 A67 = *(const ulonglong2*)&As[st][kk][ty * 16 + 12];
            u64 af[8] = {A01.x, A01.y, A23.x, A23.y, A45.x, A45.y, A67.x, A67.y};
            u64 bfr[4];
#pragma unroll
            for (int s = 0; s < 4; ++s)
                bfr[s] = *(const u64*)&Bs[st][kk][tx * 2 + s * 32];
#pragma unroll
            for (int jj = 0; jj < 8; ++jj)
#pragma unroll
                for (int s = 0; s < 4; ++s)
                    acc[jj][s] = fma2(bfr[s], af[jj], acc[jj][s]);
        }
        if (c < 15) {
            const int sn = st ^ 1;
            As[sn][qA*4+0][2*jA0] = a0.x; As[sn][qA*4+0][2*jA0+1] = a0.x;
            As[sn][qA*4+1][2*jA0] = a0.y; As[sn][qA*4+1][2*jA0+1] = a0.y;
            As[sn][qA*4+2][2*jA0] = a0.z; As[sn][qA*4+2][2*jA0+1] = a0.z;
            As[sn][qA*4+3][2*jA0] = a0.w; As[sn][qA*4+3][2*jA0+1] = a0.w;
            As[sn][qA*4+0][2*jA1] = a1.x; As[sn][qA*4+0][2*jA1+1] = a1.x;
            As[sn][qA*4+1][2*jA1] = a1.y; As[sn][qA*4+1][2*jA1+1] = a1.y;
            As[sn][qA*4+2][2*jA1] = a1.z; As[sn][qA*4+2][2*jA1+1] = a1.z;
            As[sn][qA*4+3][2*jA1] = a1.w; As[sn][qA*4+3][2*jA1+1] = a1.w;
            Bs[sn][qA*4+0][ml0] = b0v.x; Bs[sn][qA*4+1][ml0] = b0v.y;
            Bs[sn][qA*4+2][ml0] = b0v.z; Bs[sn][qA*4+3][ml0] = b0v.w;
            Bs[sn][qA*4+0][ml1] = b1v.x; Bs[sn][qA*4+1][ml1] = b1v.y;
            Bs[sn][qA*4+2][ml1] = b1v.z; Bs[sn][qA*4+3][ml1] = b1v.w;
        }
        __syncthreads();
        st ^= 1;
    }

#pragma unroll
    for (int jj = 0; jj < 8; ++jj) {
        const int row = gx * 128 + ty * 8 + jj;
        const float bv = bias[(gx & 3) * 128 + ty * 8 + jj];
#pragma unroll
        for (int s = 0; s < 4; ++s) {
            float2 v = upk2(acc[jj][s]);
            v.x += bv; v.y += bv;
            const int m = m0 + tx * 2 + s * 32;
            const size_t off = ((size_t)(m >> 6) * NG + row) * NB + (m & 63);
            *(float2*)&g_pre[off] = v;
        }
    }
}

// =====================================================================
// Phase 2: persistent recurrence.  128 CTAs x 256 threads.
// CTA(bid): rg = bid>>2 owns h-rows [16rg,16rg+16); bg = bid&3 owns
// batches [16bg,16bg+16).  Thread t: rw = t>>3 (2 gate rows), ks = t&7.
// Weights in registers.  pre double-buffered in smem: pre[step+1] is
// prefetched right after the h wait, draining during compute+publish+poll.
// Publish: h stores -> syncthreads -> t0 fence + flag (cumulative fence).
// smem: hs[64kk][8ks][20f] 40960B | pres[2][64r][16b] 8192B | red 37120B
// =====================================================================
__global__ void __launch_bounds__(256) lstm_recur(
    const float* __restrict__ Wf, const float* __restrict__ Wi,
    const float* __restrict__ Wo, const float* __restrict__ Wc)
{
    extern __shared__ float smem[];
    float* hs   = smem;                      // 64*8*20 = 10240 f (40960 B)
    float* pres = smem + 10240;              // 2*64*16 = 2048 f  (8192 B)
    u64*   red  = (u64*)(smem + 12288);      // 8*580   = 4640 u64 (37120 B)

    const int t   = threadIdx.x;
    const int bid = blockIdx.x;
    const int rg  = bid >> 2;
    const int bg  = bid & 3;
    const int rw  = t >> 3;                  // 0..31: gate-row pair
    const int ks  = t & 7;                   // k-slice of 64
    const int jj  = t >> 3, bp = t & 7;      // combine mapping (t<128)

    // per-thread pre-prefetch slot: row = t>>2 (0..63), cc = t&3
    const int prow = t >> 2, pcc = t & 3;
    const int pg   = prow >> 4, pj2 = prow & 15;
    const size_t pre_base =
        ((size_t)(pg * 512 + rg * 16 + pj2)) * 64 + bg * 16 + pcc * 4;

    // ---- load weights into registers (once) ----
    float wreg[2][64];
    {
        const int r0 = rw * 2;
        const int g  = r0 >> 4;
        const int jl = r0 & 15;
        const float* Wg = (g == 0) ? Wf : (g == 1) ? Wi : (g == 2) ? Wo : Wc;
#pragma unroll
        for (int rr = 0; rr < 2; ++rr) {
            const float* p = &Wg[(size_t)(rg * 16 + jl + rr) * 768 + ks * 64];
#pragma unroll
            for (int q = 0; q < 16; ++q) {
                float4 v = *(const float4*)(p + q * 4);
                wreg[rr][q * 4 + 0] = v.x; wreg[rr][q * 4 + 1] = v.y;
                wreg[rr][q * 4 + 2] = v.z; wreg[rr][q * 4 + 3] = v.w;
            }
        }
    }

    // ---- prefetch pre[0] into buffer 0 ----
    cpa16(pres + prow * 16 + pcc * 4, g_pre + pre_base);
    asm volatile("cp.async.commit_group;" ::: "memory");

    // ---- zero own slice of h[0], publish flag = 1 ----
    if (t < 128)
        *(float2*)&g_h[0][(rg * 16 + jj) * 64 + bg * 16 + 2 * bp] = make_float2(0.f, 0.f);
    __syncthreads();
    if (t == 0) {
        __threadfence();
        ((volatile int*)g_flags)[bg * 32 + rg] = 1;
    }

    float cva = 0.f, cvb = 0.f;
    float hma = -1e30f, hmb = -1e30f;

    for (int step = 0; step < T_SEQ; ++step) {
        const int pb = step & 1;

        // ---- wait: own column's 32 CTAs have published step's h ----
        if (t < 32) {
            volatile int* fl = g_flags + bg * 32;
            while (fl[t] < step + 1) { }
        }
        __syncthreads();

        // ---- load h column tile (32 KB); wait drains h + pre[step] ----
        {
            const float* hin = g_h[step & 1];
#pragma unroll
            for (int i = 0; i < 8; ++i) {
                const int c  = i * 256 + t;          // 16B chunk id, 0..2047
                const int k  = c >> 2, q = c & 3;
                const int kk = k & 63, kss = k >> 6;
                cpa16(hs + (kk * 8 + kss) * 20 + q * 4,
                      hin + k * 64 + bg * 16 + q * 4);
            }
            asm volatile("cp.async.commit_group;" ::: "memory");
            asm volatile("cp.async.wait_group 0;" ::: "memory");
        }
        __syncthreads();

        // ---- prefetch pre[step+1] into other buffer (drains during
        //      compute+publish+poll; waited by NEXT step's wait_group 0) ----
        {
            const int nstep = (step + 1 < T_SEQ) ? step + 1 : step;
            cpa16(pres + (pb ^ 1) * 1024 + prow * 16 + pcc * 4,
                  g_pre + (size_t)nstep * (NG * NB) + pre_base);
            asm volatile("cp.async.commit_group;" ::: "memory");
        }

        // ---- compute: 2 rows x 8 b-pairs over k-slice of 64 (w in regs) ----
        u64 acc[2][8];
#pragma unroll
        for (int rr = 0; rr < 2; ++rr)
#pragma unroll
            for (int p = 0; p < 8; ++p) acc[rr][p] = 0ull;

#pragma unroll
        for (int kk = 0; kk < 64; ++kk) {
            const float* hrow = hs + (kk * 8 + ks) * 20;
            ulonglong2 ha = *(const ulonglong2*)(hrow + 0);
            ulonglong2 hb = *(const ulonglong2*)(hrow + 4);
            ulonglong2 hc = *(const ulonglong2*)(hrow + 8);
            ulonglong2 hd = *(const ulonglong2*)(hrow + 12);
            const u64 w0 = pkdup(wreg[0][kk]);
            const u64 w1 = pkdup(wreg[1][kk]);
            acc[0][0] = fma2(ha.x, w0, acc[0][0]);
            acc[0][1] = fma2(ha.y, w0, acc[0][1]);
            acc[0][2] = fma2(hb.x, w0, acc[0][2]);
            acc[0][3] = fma2(hb.y, w0, acc[0][3]);
            acc[0][4] = fma2(hc.x, w0, acc[0][4]);
            acc[0][5] = fma2(hc.y, w0, acc[0][5]);
            acc[0][6] = fma2(hd.x, w0, acc[0][6]);
            acc[0][7] = fma2(hd.y, w0, acc[0][7]);
            acc[1][0] = fma2(ha.x, w1, acc[1][0]);
            acc[1][1] = fma2(ha.y, w1, acc[1][1]);
            acc[1][2] = fma2(hb.x, w1, acc[1][2]);
            acc[1][3] = fma2(hb.y, w1, acc[1][3]);
            acc[1][4] = fma2(hc.x, w1, acc[1][4]);
            acc[1][5] = fma2(hc.y, w1, acc[1][5]);
            acc[1][6] = fma2(hd.x, w1, acc[1][6]);
            acc[1][7] = fma2(hd.y, w1, acc[1][7]);
        }

        // ---- store k-partials: red[ks*580 + r*9 + p] ----
#pragma unroll
        for (int rr = 0; rr < 2; ++rr)
#pragma unroll
            for (int p = 0; p < 8; ++p)
                red[ks * 580 + (rw * 2 + rr) * 9 + p] = acc[rr][p];
        __syncthreads();

        // ---- combine + pointwise cell (threads 0..127) ----
        if (t < 128) {
            float2 gs[4];
#pragma unroll
            for (int g = 0; g < 4; ++g) {
                const int rbase = (g * 16 + jj) * 9 + bp;
                u64 s0 = add2(red[0 * 580 + rbase], red[1 * 580 + rbase]);
                u64 s1 = add2(red[2 * 580 + rbase], red[3 * 580 + rbase]);
                u64 s2 = add2(red[4 * 580 + rbase], red[5 * 580 + rbase]);
                u64 s3 = add2(red[6 * 580 + rbase], red[7 * 580 + rbase]);
                u64 sum = add2(add2(s0, s1), add2(s2, s3));
                float2 v  = upk2(sum);
                float2 pv = *(const float2*)&pres[pb * 1024 + (g * 16 + jj) * 16 + 2 * bp];
                gs[g] = make_float2(v.x + pv.x, v.y + pv.y);
            }
            const float fa = sigf(gs[0].x), fb = sigf(gs[0].y);
            const float ia = sigf(gs[1].x), ib = sigf(gs[1].y);
            const float oa = sigf(gs[2].x), ob = sigf(gs[2].y);
            const float ga = tanh_fast(gs[3].x), gb = tanh_fast(gs[3].y);
            cva = fa * cva + ia * ga;
            cvb = fb * cvb + ib * gb;
            const float ha = oa * tanh_fast(cva);
            const float hb = ob * tanh_fast(cvb);
            hma = fmaxf(hma, ha);
            hmb = fmaxf(hmb, hb);
            *(float2*)&g_h[(step + 1) & 1][(rg * 16 + jj) * 64 + bg * 16 + 2 * bp] =
                make_float2(ha, hb);
        }
        __syncthreads();
        if (t == 0) {
            __threadfence();
            ((volatile int*)g_flags)[bg * 32 + rg] = step + 2;
        }
    }

    // ---- epilogue: write hmax ----
    if (t < 128)
        *(float2*)&g_hmax[(rg * 16 + jj) * 64 + bg * 16 + 2 * bp] = make_float2(hma, hmb);

    // drain the last pre prefetch group before exit
    asm volatile("cp.async.wait_group 0;" ::: "memory");

    // two centralized sense barriers (even count -> g_sense restored),
    // flag reset in between: no CTA can still be polling when reset lands.
    int sense = 0;
#pragma unroll
    for (int rep = 0; rep < 2; ++rep) {
        __threadfence();
        __syncthreads();
        if (t == 0) {
            sense ^= 1;
            if (atomicAdd(&g_count, 1) == RECUR_CTAS - 1) {
                *(volatile int*)&g_count = 0;
                __threadfence();
                *(volatile int*)&g_sense = sense;
            } else {
                while (*(volatile int*)&g_sense != sense) { }
            }
            __threadfence();
        }
        __syncthreads();
        if (rep == 0 && t == 0) g_flags[bg * 32 + rg] = 0;
    }
}

// =====================================================================
// Phase 3: logits[b][c] = fc_b[c] + sum_j hmax[j][b] * fc_w[c][j]
// =====================================================================
__global__ void fc_kernel(const float* __restrict__ fcw,
                          const float* __restrict__ fcb,
                          float* __restrict__ out)
{
    const int t = threadIdx.x;
    const int b = t & 63, c = t >> 6;
    float acc = 0.f;
#pragma unroll 8
    for (int j = 0; j < NH; ++j)
        acc += g_hmax[j * 64 + b] * fcw[c * NH + j];
    out[b * 4 + c] = acc + fcb[c];
}

// =====================================================================
extern "C" void kernel_launch(void* const* d_in, const int* in_sizes, int n_in,
                              void* d_out, int out_size)
{
    (void)in_sizes; (void)n_in; (void)out_size;
    const int*   ids = (const int*)  d_in[0];
    const float* emb = (const float*)d_in[1];
    const float* Wf  = (const float*)d_in[2];
    const float* bf  = (const float*)d_in[3];
    const float* Wi  = (const float*)d_in[4];
    const float* bi  = (const float*)d_in[5];
    const float* Wo  = (const float*)d_in[6];
    const float* bo  = (const float*)d_in[7];
    const float* Wc  = (const float*)d_in[8];
    const float* bc  = (const float*)d_in[9];
    const float* fcw = (const float*)d_in[10];
    const float* fcb = (const float*)d_in[11];
    float* out = (float*)d_out;

    // hs 40960 + pres 8192 + red 37120 = 86272 B
    const int recur_smem = 86272;
    cudaFuncSetAttribute(lstm_recur, cudaFuncAttributeMaxDynamicSharedMemorySize, recur_smem);

    pre_gemm<<<dim3(16, 256), 256>>>(ids, emb, Wf, bf, Wi, bi, Wo, bo, Wc, bc);
    lstm_recur<<<RECUR_CTAS, 256, recur_smem>>>(Wf, Wi, Wo, Wc);
    fc_kernel<<<1, 256>>>(fcw, fcb, out);
}

// round 14
// speedup vs baseline: 1.6036x; 1.0739x over previous
#include <cuda_runtime.h>
#include <cuda_bf16.h>

// ---------------------------------------------------------------------------
// DisableGateLSTM: B=64, T=512, E=256, H=512, C=4
// Phase 1: pre-GEMM into g_pre laid out [t][bg][rg][g][16j][16b] (4KB blocks)
// Phase 2: persistent recurrence, 128 CTAs = 32 rg x 4 bg.
//          h tile (32KB contiguous) + pre tile (4KB) fetched via
//          cp.async.bulk (TMA) with mbarrier completion  -> no per-thread
//          load issue cost.  Weights in registers.  Per-column flag barrier.
// Phase 3: logits = (max_t h) @ fc_w^T + fc_b
// ---------------------------------------------------------------------------

#define T_SEQ 512
#define NB    64
#define NE    256
#define NH    512
#define NG    2048
#define RECUR_CTAS 128

typedef unsigned long long u64;

// g_pre[t][bg][rg][g][jj][bb] : block (t,bg,rg) = 4*16*16 floats = 4KB
static __device__ float g_pre[(size_t)T_SEQ * 4 * 32 * 4 * 16 * 16];
// g_h[buf][bg][j][bb] : per-(buf,bg) block = 512*16 floats = 32KB contiguous
static __device__ float g_h[2][4][NH][16];
static __device__ float g_hmax[NH * NB];                  // [j][b] (old layout)
static __device__ int   g_flags[RECUR_CTAS];              // [bg][rg] progress
static __device__ int   g_count;                          // epilogue barrier
static __device__ int   g_sense;

// ---------------- f32x2 helpers ----------------
static __device__ __forceinline__ u64 fma2(u64 a, u64 b, u64 c) {
    u64 d;
    asm("fma.rn.f32x2 %0, %1, %2, %3;" : "=l"(d) : "l"(a), "l"(b), "l"(c));
    return d;
}
static __device__ __forceinline__ u64 add2(u64 a, u64 b) {
    u64 d;
    asm("add.rn.f32x2 %0, %1, %2;" : "=l"(d) : "l"(a), "l"(b));
    return d;
}
static __device__ __forceinline__ u64 pkdup(float a) {
    u64 r; asm("mov.b64 %0, {%1, %1};" : "=l"(r) : "f"(a)); return r;
}
static __device__ __forceinline__ float2 upk2(u64 a) {
    float2 f;
    asm("mov.b64 {%0, %1}, %2;" : "=f"(f.x), "=f"(f.y) : "l"(a));
    return f;
}
static __device__ __forceinline__ float sigf(float x) {
    return 1.f / (1.f + __expf(-x));
}
static __device__ __forceinline__ float tanh_fast(float x) {
    return 2.f / (1.f + __expf(-2.f * x)) - 1.f;
}

// ---------------- mbarrier / bulk-copy helpers ----------------
static __device__ __forceinline__ unsigned smem_u32(const void* p) {
    return (unsigned)__cvta_generic_to_shared(p);
}
static __device__ __forceinline__ void mbar_init(unsigned mbar, unsigned cnt) {
    asm volatile("mbarrier.init.shared.b64 [%0], %1;" :: "r"(mbar), "r"(cnt) : "memory");
}
static __device__ __forceinline__ void mbar_expect_tx(unsigned mbar, unsigned bytes) {
    asm volatile("mbarrier.arrive.expect_tx.shared.b64 _, [%0], %1;"
                 :: "r"(mbar), "r"(bytes) : "memory");
}
static __device__ __forceinline__ void bulk_g2s(unsigned sdst, const void* gsrc,
                                                unsigned bytes, unsigned mbar) {
    asm volatile(
        "cp.async.bulk.shared::cta.global.mbarrier::complete_tx::bytes [%0], [%1], %2, [%3];"
        :: "r"(sdst), "l"(gsrc), "r"(bytes), "r"(mbar) : "memory");
}
static __device__ __forceinline__ void mbar_wait(unsigned mbar, int parity) {
    asm volatile(
        "{\n\t"
        ".reg .pred P;\n\t"
        "W_%=:\n\t"
        "mbarrier.try_wait.parity.acquire.cta.shared::cta.b64 P, [%0], %1;\n\t"
        "@!P bra W_%=;\n\t"
        "}"
        :: "r"(mbar), "r"(parity) : "memory");
}

// =====================================================================
// Phase 1: pre-GEMM (R11 body; only the epilogue addressing changed)
// =====================================================================
__global__ void __launch_bounds__(256, 2) pre_gemm(
    const int* __restrict__ ids, const float* __restrict__ emb,
    const float* __restrict__ Wf, const float* __restrict__ bf,
    const float* __restrict__ Wi, const float* __restrict__ bi,
    const float* __restrict__ Wo, const float* __restrict__ bo,
    const float* __restrict__ Wc, const float* __restrict__ bc)
{
    __shared__ float As[2][16][256];   // [kk][2*j] duplicated pairs
    __shared__ float Bs[2][16][128];   // [kk][m]

    const int t  = threadIdx.x;
    const int gx = blockIdx.x;
    const int m0 = blockIdx.y * 128;
    const int tx = t & 15, ty = t >> 4;

    const float* W    = (gx < 4) ? Wf : (gx < 8) ? Wi : (gx < 12) ? Wo : Wc;
    const float* bias = (gx < 4) ? bf : (gx < 8) ? bi : (gx < 12) ? bo : bc;
    const int jg0 = (gx & 3) * 128;

    const int jA0 = t >> 2;
    const int jA1 = jA0 + 64;
    const int qA  = t & 3;
    const int ml0 = t >> 2;
    const int ml1 = ml0 + 64;
    const int mg0 = m0 + ml0, mg1 = m0 + ml1;
    const int id0 = ids[(mg0 & 63) * T_SEQ + (mg0 >> 6)];
    const int id1 = ids[(mg1 & 63) * T_SEQ + (mg1 >> 6)];

    u64 acc[8][4];
#pragma unroll
    for (int jj = 0; jj < 8; ++jj)
#pragma unroll
        for (int s = 0; s < 4; ++s) acc[jj][s] = 0ull;

    float4 a0, a1, b0v, b1v;
    {
        const int k0 = 0;
        a0  = *(const float4*)&W[(size_t)(jg0 + jA0) * 768 + 512 + k0 + qA * 4];
        a1  = *(const float4*)&W[(size_t)(jg0 + jA1) * 768 + 512 + k0 + qA * 4];
        b0v = *(const float4*)&emb[(size_t)id0 * NE + k0 + qA * 4];
        b1v = *(const float4*)&emb[(size_t)id1 * NE + k0 + qA * 4];
    }
    {
        const int st = 0;
        As[st][qA*4+0][2*jA0] = a0.x; As[st][qA*4+0][2*jA0+1] = a0.x;
        As[st][qA*4+1][2*jA0] = a0.y; As[st][qA*4+1][2*jA0+1] = a0.y;
        As[st][qA*4+2][2*jA0] = a0.z; As[st][qA*4+2][2*jA0+1] = a0.z;
        As[st][qA*4+3][2*jA0] = a0.w; As[st][qA*4+3][2*jA0+1] = a0.w;
        As[st][qA*4+0][2*jA1] = a1.x; As[st][qA*4+0][2*jA1+1] = a1.x;
        As[st][qA*4+1][2*jA1] = a1.y; As[st][qA*4+1][2*jA1+1] = a1.y;
        As[st][qA*4+2][2*jA1] = a1.z; As[st][qA*4+2][2*jA1+1] = a1.z;
        As[st][qA*4+3][2*jA1] = a1.w; As[st][qA*4+3][2*jA1+1] = a1.w;
        Bs[st][qA*4+0][ml0] = b0v.x; Bs[st][qA*4+1][ml0] = b0v.y;
        Bs[st][qA*4+2][ml0] = b0v.z; Bs[st][qA*4+3][ml0] = b0v.w;
        Bs[st][qA*4+0][ml1] = b1v.x; Bs[st][qA*4+1][ml1] = b1v.y;
        Bs[st][qA*4+2][ml1] = b1v.z; Bs[st][qA*4+3][ml1] = b1v.w;
    }
    __syncthreads();

    int st = 0;
    for (int c = 0; c < 16; ++c) {
        if (c < 15) {
            const int k0 = (c + 1) * 16;
            a0  = *(const float4*)&W[(size_t)(jg0 + jA0) * 768 + 512 + k0 + qA * 4];
            a1  = *(const float4*)&W[(size_t)(jg0 + jA1) * 768 + 512 + k0 + qA * 4];
            b0v = *(const float4*)&emb[(size_t)id0 * NE + k0 + qA * 4];
            b1v = *(const float4*)&emb[(size_t)id1 * NE + k0 + qA * 4];
        }
#pragma unroll 4
        for (int kk = 0; kk < 16; ++kk) {
            ulonglong2 A01 = *(const ulonglong2*)&As[st][kk][ty * 16 + 0];
            ulonglong2 A23 = *(const ulonglong2*)&As[st][kk][ty * 16 + 4];
            ulonglong2 A45 = *(const ulonglong2*)&As[st][kk][ty * 16 + 8];
            ulonglong2 A67 = *(const ulonglong2*)&As[st][kk][ty * 16 + 12];
            u64 af[8] = {A01.x, A01.y, A23.x, A23.y, A45.x, A45.y, A67.x, A67.y};
            u64 bfr[4];
#pragma unroll
            for (int s = 0; s < 4; ++s)
                bfr[s] = *(const u64*)&Bs[st][kk][tx * 2 + s * 32];
#pragma unroll
            for (int jj = 0; jj < 8; ++jj)
#pragma unroll
                for (int s = 0; s < 4; ++s)
                    acc[jj][s] = fma2(bfr[s], af[jj], acc[jj][s]);
        }
        if (c < 15) {
            const int sn = st ^ 1;
            As[sn][qA*4+0][2*jA0] = a0.x; As[sn][qA*4+0][2*jA0+1] = a0.x;
            As[sn][qA*4+1][2*jA0] = a0.y; As[sn][qA*4+1][2*jA0+1] = a0.y;
            As[sn][qA*4+2][2*jA0] = a0.z; As[sn][qA*4+2][2*jA0+1] = a0.z;
            As[sn][qA*4+3][2*jA0] = a0.w; As[sn][qA*4+3][2*jA0+1] = a0.w;
            As[sn][qA*4+0][2*jA1] = a1.x; As[sn][qA*4+0][2*jA1+1] = a1.x;
            As[sn][qA*4+1][2*jA1] = a1.y; As[sn][qA*4+1][2*jA1+1] = a1.y;
            As[sn][qA*4+2][2*jA1] = a1.z; As[sn][qA*4+2][2*jA1+1] = a1.z;
            As[sn][qA*4+3][2*jA1] = a1.w; As[sn][qA*4+3][2*jA1+1] = a1.w;
            Bs[sn][qA*4+0][ml0] = b0v.x; Bs[sn][qA*4+1][ml0] = b0v.y;
            Bs[sn][qA*4+2][ml0] = b0v.z; Bs[sn][qA*4+3][ml0] = b0v.w;
            Bs[sn][qA*4+0][ml1] = b1v.x; Bs[sn][qA*4+1][ml1] = b1v.y;
            Bs[sn][qA*4+2][ml1] = b1v.z; Bs[sn][qA*4+3][ml1] = b1v.w;
        }
        __syncthreads();
        st ^= 1;
    }

    // epilogue: write into [t][bg][rg][g][jj][bb] blocks
#pragma unroll
    for (int jj = 0; jj < 8; ++jj) {
        const int row = gx * 128 + ty * 8 + jj;   // 0..2047
        const int g   = row >> 9;
        const int jg  = row & 511;
        const int rg  = jg >> 4;
        const int j16 = jg & 15;
        const float bv = bias[(gx & 3) * 128 + ty * 8 + jj];
#pragma unroll
        for (int s = 0; s < 4; ++s) {
            float2 v = upk2(acc[jj][s]);
            v.x += bv; v.y += bv;
            const int m  = m0 + tx * 2 + s * 32;
            const int tt = m >> 6, b = m & 63;
            const int bg = b >> 4, bb = b & 15;
            const size_t off =
                ((((size_t)tt * 4 + bg) * 32 + rg) * 4 + g) * 256 + j16 * 16 + bb;
            *(float2*)&g_pre[off] = v;
        }
    }
}

// =====================================================================
// Phase 2: persistent recurrence.  128 CTAs x 256 threads.
// CTA(bid): rg = bid>>2 owns h-rows [16rg,16rg+16); bg = bid&3 owns
// batches [16bg,16bg+16).  Thread t: rw = t>>3 (2 gate rows), ks = t&7.
// h (32KB) + pre (4KB, double-buffered) arrive via cp.async.bulk + mbarrier.
// smem bytes: [0,24) mbars | [128,32896) hs | [32896,41088) pres | red after.
// hs linear [k][16b]; LDS uses per-ks chunk rotation => conflict-free LDS.64.
// =====================================================================
__global__ void __launch_bounds__(256, 1) lstm_recur(
    const float* __restrict__ Wf, const float* __restrict__ Wi,
    const float* __restrict__ Wo, const float* __restrict__ Wc)
{
    extern __shared__ char smem[];
    const unsigned mb_h  = smem_u32(smem + 0);
    const unsigned mb_p0 = smem_u32(smem + 8);
    const unsigned mb_p1 = smem_u32(smem + 16);
    const unsigned hs_s   = smem_u32(smem + 128);
    const unsigned pres_s = smem_u32(smem + 32896);
    const u64*   hs64 = (const u64*)(smem + 128);
    const float* pres = (const float*)(smem + 32896);
    u64*         red  = (u64*)(smem + 41088);          // 8*580 u64 = 37120 B

    const int t   = threadIdx.x;
    const int bid = blockIdx.x;
    const int rg  = bid >> 2;
    const int bg  = bid & 3;
    const int rw  = t >> 3;                  // 0..31: gate-row pair
    const int ks  = t & 7;                   // k-slice of 64
    const int jj  = t >> 3, bp = t & 7;      // combine mapping (t<128)

    // ---- load weights into registers (once) ----
    float wreg[2][64];
    {
        const int r0 = rw * 2;
        const int g  = r0 >> 4;
        const int jl = r0 & 15;
        const float* Wg = (g == 0) ? Wf : (g == 1) ? Wi : (g == 2) ? Wo : Wc;
#pragma unroll
        for (int rr = 0; rr < 2; ++rr) {
            const float* p = &Wg[(size_t)(rg * 16 + jl + rr) * 768 + ks * 64];
#pragma unroll
            for (int q = 0; q < 16; ++q) {
                float4 v = *(const float4*)(p + q * 4);
                wreg[rr][q * 4 + 0] = v.x; wreg[rr][q * 4 + 1] = v.y;
                wreg[rr][q * 4 + 2] = v.z; wreg[rr][q * 4 + 3] = v.w;
            }
        }
    }

    // rotated chunk offsets: thread (rw,ks) reads pair p=(ks+i)&7 of its rows
    int off8[8], p8[8];
#pragma unroll
    for (int i = 0; i < 8; ++i) {
        p8[i]   = (ks + i) & 7;
        off8[i] = ks * 512 + p8[i];          // (ks*64 rows)*8 u64 + pair
    }

    // ---- init mbarriers, prefetch pre[0] into buffer 0 ----
    if (t == 0) {
        mbar_init(mb_h, 1);
        mbar_init(mb_p0, 1);
        mbar_init(mb_p1, 1);
    }
    __syncthreads();
    if (t == 0) {
        mbar_expect_tx(mb_p0, 4096);
        bulk_g2s(pres_s, g_pre + (((size_t)0 * 4 + bg) * 32 + rg) * 1024, 4096, mb_p0);
    }

    // ---- zero own slice of h[0], publish flag = 1 ----
    if (t < 128) {
        *(float2*)&g_h[0][bg][rg * 16 + jj][2 * bp] = make_float2(0.f, 0.f);
        __threadfence();
    }
    __syncthreads();
    if (t == 0) ((volatile int*)g_flags)[bg * 32 + rg] = 1;

    float cva = 0.f, cvb = 0.f;
    float hma = -1e30f, hmb = -1e30f;
    int pre_par[2] = {0, 0};

    for (int step = 0; step < T_SEQ; ++step) {
        const int pb = step & 1;

        // ---- wait: own column's 32 CTAs have published step's h ----
        if (t < 32) {
            volatile int* fl = g_flags + bg * 32;
            while (fl[t] < step + 1) { }
        }
        __syncthreads();

        // ---- issue bulks: h[step] (32KB) + pre[step+1] (4KB) ----
        if (t == 0) {
            mbar_expect_tx(mb_h, 32768);
            bulk_g2s(hs_s, &g_h[step & 1][bg][0][0], 32768, mb_h);
            const int ns = (step + 1 < T_SEQ) ? step + 1 : T_SEQ - 1;
            const unsigned mbp = (pb ^ 1) ? mb_p1 : mb_p0;
            mbar_expect_tx(mbp, 4096);
            bulk_g2s(pres_s + (pb ^ 1) * 4096,
                     g_pre + (((size_t)ns * 4 + bg) * 32 + rg) * 1024, 4096, mbp);
        }

        // ---- wait h tile ----
        mbar_wait(mb_h, step & 1);

        // ---- compute: 2 rows x 8 rotated b-pairs over k-slice of 64 ----
        u64 acc0[8], acc1[8];
#pragma unroll
        for (int i = 0; i < 8; ++i) { acc0[i] = 0ull; acc1[i] = 0ull; }

#pragma unroll
        for (int kk = 0; kk < 64; ++kk) {
            const u64 w0 = pkdup(wreg[0][kk]);
            const u64 w1 = pkdup(wreg[1][kk]);
#pragma unroll
            for (int i = 0; i < 8; ++i) {
                const u64 hv = hs64[off8[i] + kk * 8];
                acc0[i] = fma2(hv, w0, acc0[i]);
                acc1[i] = fma2(hv, w1, acc1[i]);
            }
        }

        // ---- store k-partials to rotated logical slots ----
        {
            const int rbase0 = ks * 580 + (rw * 2 + 0) * 9;
            const int rbase1 = ks * 580 + (rw * 2 + 1) * 9;
#pragma unroll
            for (int i = 0; i < 8; ++i) {
                red[rbase0 + p8[i]] = acc0[i];
                red[rbase1 + p8[i]] = acc1[i];
            }
        }

        // ---- wait pre[step] (combiners only; parity tracked by all) ----
        if (t < 128) {
            const unsigned mbp = pb ? mb_p1 : mb_p0;
            mbar_wait(mbp, pre_par[pb]);
        }
        pre_par[pb] ^= 1;
        __syncthreads();

        // ---- combine + pointwise cell (threads 0..127) ----
        if (t < 128) {
            float2 gs[4];
#pragma unroll
            for (int g = 0; g < 4; ++g) {
                const int rbase = (g * 16 + jj) * 9 + bp;
                u64 s0 = add2(red[0 * 580 + rbase], red[1 * 580 + rbase]);
                u64 s1 = add2(red[2 * 580 + rbase], red[3 * 580 + rbase]);
                u64 s2 = add2(red[4 * 580 + rbase], red[5 * 580 + rbase]);
                u64 s3 = add2(red[6 * 580 + rbase], red[7 * 580 + rbase]);
                u64 sum = add2(add2(s0, s1), add2(s2, s3));
                float2 v  = upk2(sum);
                float2 pv = *(const float2*)&pres[pb * 1024 + (g * 16 + jj) * 16 + 2 * bp];
                gs[g] = make_float2(v.x + pv.x, v.y + pv.y);
            }
            const float fa = sigf(gs[0].x), fb = sigf(gs[0].y);
            const float ia = sigf(gs[1].x), ib = sigf(gs[1].y);
            const float oa = sigf(gs[2].x), ob = sigf(gs[2].y);
            const float ga = tanh_fast(gs[3].x), gb = tanh_fast(gs[3].y);
            cva = fa * cva + ia * ga;
            cvb = fb * cvb + ib * gb;
            const float ha = oa * tanh_fast(cva);
            const float hb = ob * tanh_fast(cvb);
            hma = fmaxf(hma, ha);
            hmb = fmaxf(hmb, hb);
            *(float2*)&g_h[(step + 1) & 1][bg][rg * 16 + jj][2 * bp] =
                make_float2(ha, hb);
            __threadfence();
        }
        __syncthreads();
        if (t == 0) ((volatile int*)g_flags)[bg * 32 + rg] = step + 2;
    }

    // ---- drain the final outstanding pre bulk (into buf 0) ----
    if (t == 0) mbar_wait(mb_p0, pre_par[0]);

    // ---- epilogue: write hmax (old [j][b] layout) ----
    if (t < 128)
        *(float2*)&g_hmax[(rg * 16 + jj) * 64 + bg * 16 + 2 * bp] = make_float2(hma, hmb);

    // two centralized sense barriers (even count -> g_sense restored),
    // flag reset in between: no CTA can still be polling when reset lands.
    int sense = 0;
#pragma unroll
    for (int rep = 0; rep < 2; ++rep) {
        __threadfence();
        __syncthreads();
        if (t == 0) {
            sense ^= 1;
            if (atomicAdd(&g_count, 1) == RECUR_CTAS - 1) {
                *(volatile int*)&g_count = 0;
                __threadfence();
                *(volatile int*)&g_sense = sense;
            } else {
                while (*(volatile int*)&g_sense != sense) { }
            }
            __threadfence();
        }
        __syncthreads();
        if (rep == 0 && t == 0) g_flags[bg * 32 + rg] = 0;
    }
}

// =====================================================================
// Phase 3: logits[b][c] = fc_b[c] + sum_j hmax[j][b] * fc_w[c][j]
// =====================================================================
__global__ void fc_kernel(const float* __restrict__ fcw,
                          const float* __restrict__ fcb,
                          float* __restrict__ out)
{
    const int t = threadIdx.x;
    const int b = t & 63, c = t >> 6;
    float acc = 0.f;
#pragma unroll 8
    for (int j = 0; j < NH; ++j)
        acc += g_hmax[j * 64 + b] * fcw[c * NH + j];
    out[b * 4 + c] = acc + fcb[c];
}

// =====================================================================
extern "C" void kernel_launch(void* const* d_in, const int* in_sizes, int n_in,
                              void* d_out, int out_size)
{
    (void)in_sizes; (void)n_in; (void)out_size;
    const int*   ids = (const int*)  d_in[0];
    const float* emb = (const float*)d_in[1];
    const float* Wf  = (const float*)d_in[2];
    const float* bf  = (const float*)d_in[3];
    const float* Wi  = (const float*)d_in[4];
    const float* bi  = (const float*)d_in[5];
    const float* Wo  = (const float*)d_in[6];
    const float* bo  = (const float*)d_in[7];
    const float* Wc  = (const float*)d_in[8];
    const float* bc  = (const float*)d_in[9];
    const float* fcw = (const float*)d_in[10];
    const float* fcb = (const float*)d_in[11];
    float* out = (float*)d_out;

    // mbars 128 + hs 32768 + pres 8192 + red 37120 = 78208 B
    const int recur_smem = 78208;
    cudaFuncSetAttribute(lstm_recur, cudaFuncAttributeMaxDynamicSharedMemorySize, recur_smem);

    pre_gemm<<<dim3(16, 256), 256>>>(ids, emb, Wf, bf, Wi, bi, Wo, bo, Wc, bc);
    lstm_recur<<<RECUR_CTAS, 256, recur_smem>>>(Wf, Wi, Wo, Wc);
    fc_kernel<<<1, 256>>>(fcw, fcb, out);
}